// round 15
// baseline (speedup 1.0000x reference)
#include <cuda_runtime.h>
#include <cstddef>

#define N_NODES 200000
#define FEAT    480
#define EPS     1e-5f

// Row layout (480 fp32 = 120 float4; vec4 index v = lane + 32k):
//   k=0: elems [0,128)    -> scalar layernorm, w[0:128], b[0:128]
//   k=1: elems [128,256)  -> field2 (mul=64,d=3), w[128 + (e-128)/3]
//   k=2: elems [256,384)  -> lane<16: field2 ; lane>=16: field3 (mul=32,d=5), w[192+(e-320)/5]
//   k=3: elems [384,480)  -> field3, only lanes 0..23 valid

struct RowBuf { float4 x0, x1, x2, x3; };

__device__ __forceinline__ void load_row(const float* __restrict__ in, int row,
                                         int lane, bool tail, RowBuf& rb)
{
    const float4* rin = (const float4*)(in + (size_t)row * FEAT);
    rb.x0 = __ldcs(&rin[lane]);
    rb.x1 = __ldcs(&rin[lane + 32]);
    rb.x2 = __ldcs(&rin[lane + 64]);
    rb.x3 = tail ? __ldcs(&rin[lane + 96]) : make_float4(0.f, 0.f, 0.f, 0.f);
}

__device__ __forceinline__ void process_row(float* __restrict__ out, int row,
                                            int lane, bool tail, bool k2_is2,
                                            const float* wr, const float* br,
                                            const RowBuf& rb)
{
    const float4 x0 = rb.x0, x1 = rb.x1, x2 = rb.x2, x3 = rb.x3;

    // per-thread partial sums
    float s1  = x0.x + x0.y + x0.z + x0.w;
    float ss1 = x0.x * x0.x + x0.y * x0.y + x0.z * x0.z + x0.w * x0.w;
    float d1  = x1.x * x1.x + x1.y * x1.y + x1.z * x1.z + x1.w * x1.w;
    float d2  = x2.x * x2.x + x2.y * x2.y + x2.z * x2.z + x2.w * x2.w;
    float d3  = x3.x * x3.x + x3.y * x3.y + x3.z * x3.z + x3.w * x3.w;

    float ss2 = d1 + (k2_is2 ? d2 : 0.0f);
    float ss3 = d3 + (k2_is2 ? 0.0f : d2);

    // warp butterfly reduction: 4 independent chains, SHFLs issued
    // back-to-back per stage so their latency overlaps.
#pragma unroll
    for (int o = 16; o > 0; o >>= 1) {
        const float t1 = __shfl_xor_sync(0xFFFFFFFFu, s1,  o);
        const float t2 = __shfl_xor_sync(0xFFFFFFFFu, ss1, o);
        const float t3 = __shfl_xor_sync(0xFFFFFFFFu, ss2, o);
        const float t4 = __shfl_xor_sync(0xFFFFFFFFu, ss3, o);
        s1 += t1; ss1 += t2; ss2 += t3; ss3 += t4;
    }

    const float mean = s1 * (1.0f / 128.0f);
    const float var  = ss1 * (1.0f / 128.0f) - mean * mean;
    const float inv1 = rsqrtf(var + EPS);
    const float inv2 = rsqrtf(ss2 * (1.0f / 192.0f) + EPS);
    const float inv3 = rsqrtf(ss3 * (1.0f / 160.0f) + EPS);

    float4* rout = (float4*)(out + (size_t)row * FEAT);

    float4 y0;
    y0.x = (x0.x - mean) * (inv1 * wr[0]) + br[0];
    y0.y = (x0.y - mean) * (inv1 * wr[1]) + br[1];
    y0.z = (x0.z - mean) * (inv1 * wr[2]) + br[2];
    y0.w = (x0.w - mean) * (inv1 * wr[3]) + br[3];
    __stcs(&rout[lane], y0);

    float4 y1;
    y1.x = x1.x * (inv2 * wr[4]);
    y1.y = x1.y * (inv2 * wr[5]);
    y1.z = x1.z * (inv2 * wr[6]);
    y1.w = x1.w * (inv2 * wr[7]);
    __stcs(&rout[lane + 32], y1);

    const float invk2 = k2_is2 ? inv2 : inv3;
    float4 y2;
    y2.x = x2.x * (invk2 * wr[8]);
    y2.y = x2.y * (invk2 * wr[9]);
    y2.z = x2.z * (invk2 * wr[10]);
    y2.w = x2.w * (invk2 * wr[11]);
    __stcs(&rout[lane + 64], y2);

    if (tail) {
        float4 y3;
        y3.x = x3.x * (inv3 * wr[12]);
        y3.y = x3.y * (inv3 * wr[13]);
        y3.z = x3.z * (inv3 * wr[14]);
        y3.w = x3.w * (inv3 * wr[15]);
        __stcs(&rout[lane + 96], y3);
    }
}

__global__ __launch_bounds__(256, 4)
void eqln_kernel(const float* __restrict__ in,
                 const float* __restrict__ w,
                 const float* __restrict__ b,
                 float* __restrict__ out)
{
    const int lane   = threadIdx.x & 31;
    const int warp   = (int)((blockIdx.x * blockDim.x + threadIdx.x) >> 5);
    const int nwarps = (int)((gridDim.x * blockDim.x) >> 5);

    // per-thread weights/biases in registers, amortized across ~42 rows
    float wr[16];
    float br[4];
#pragma unroll
    for (int k = 0; k < 4; k++) {
#pragma unroll
        for (int c = 0; c < 4; c++) {
            int e = 4 * (lane + 32 * k) + c;
            float wv = 0.0f;
            if (e < 128)       wv = __ldg(&w[e]);
            else if (e < 320)  wv = __ldg(&w[128 + (e - 128) / 3]);
            else if (e < 480)  wv = __ldg(&w[192 + (e - 320) / 5]);
            wr[4 * k + c] = wv;
        }
    }
#pragma unroll
    for (int c = 0; c < 4; c++) br[c] = __ldg(&b[4 * lane + c]);

    const bool tail   = (lane < 24);
    const bool k2_is2 = (lane < 16);

    // Exactly-balanced contiguous partition: warp w gets base + (w < rem)
    // consecutive rows. Removes the 1-row tail-wave imbalance of grid-stride,
    // and consecutive rows (+1920B) give per-warp DRAM page locality.
    const int base = N_NODES / nwarps;
    const int rem  = N_NODES - base * nwarps;
    int row = warp * base + (warp < rem ? warp : rem);
    const int end = row + base + (warp < rem ? 1 : 0);
    if (row >= end) return;

    RowBuf A, B;
    load_row(in, row, lane, tail, A);
    int next = row + 1;

    // Ping-pong double buffer: next row's loads issue before current row's
    // reduction, so reduce/epilogue latency overlaps the next load batch.
    while (true) {
        if (next < end) load_row(in, next, lane, tail, B);
        process_row(out, row, lane, tail, k2_is2, wr, br, A);
        if (next >= end) break;
        row = next; next++;

        if (next < end) load_row(in, next, lane, tail, A);
        process_row(out, row, lane, tail, k2_is2, wr, br, B);
        if (next >= end) break;
        row = next; next++;
    }
}

extern "C" void kernel_launch(void* const* d_in, const int* in_sizes, int n_in,
                              void* d_out, int out_size)
{
    const float* node_input    = (const float*)d_in[0];   // (200000, 480) f32
    const float* affine_weight = (const float*)d_in[1];   // (224,) f32
    const float* affine_bias   = (const float*)d_in[2];   // (128,) f32
    float* out = (float*)d_out;

    const int threads = 256;
    const int blocks  = 148 * 4;   // 592 blocks -> 4736 warps, 4 CTAs/SM
    eqln_kernel<<<blocks, threads>>>(node_input, affine_weight, affine_bias, out);
}

// round 16
// speedup vs baseline: 1.0647x; 1.0647x over previous
#include <cuda_runtime.h>
#include <cstddef>

#define N_NODES 200000
#define FEAT    480
#define EPS     1e-5f

// Row layout (480 fp32 = 120 float4; vec4 index v = lane + 32k):
//   k=0: elems [0,128)    -> scalar layernorm, w[0:128], b[0:128]
//   k=1: elems [128,256)  -> field2 (mul=64,d=3), w[128 + (e-128)/3]
//   k=2: elems [256,384)  -> lane<16: field2 ; lane>=16: field3 (mul=32,d=5), w[192+(e-320)/5]
//   k=3: elems [384,480)  -> field3, only lanes 0..23 valid

struct RowBuf { float4 x0, x1, x2, x3; };

__device__ __forceinline__ void load_row(const float* __restrict__ in, int row,
                                         int lane, bool tail, RowBuf& rb)
{
    const float4* rin = (const float4*)(in + (size_t)row * FEAT);
    rb.x0 = __ldcs(&rin[lane]);
    rb.x1 = __ldcs(&rin[lane + 32]);
    rb.x2 = __ldcs(&rin[lane + 64]);
    rb.x3 = tail ? __ldcs(&rin[lane + 96]) : make_float4(0.f, 0.f, 0.f, 0.f);
}

__device__ __forceinline__ void process_row(float* __restrict__ out, int row,
                                            int lane, bool tail, bool k2_is2,
                                            const float* wr, const float* br,
                                            const RowBuf& rb)
{
    const float4 x0 = rb.x0, x1 = rb.x1, x2 = rb.x2, x3 = rb.x3;

    // per-thread partial sums
    float s1  = x0.x + x0.y + x0.z + x0.w;
    float ss1 = x0.x * x0.x + x0.y * x0.y + x0.z * x0.z + x0.w * x0.w;
    float d1  = x1.x * x1.x + x1.y * x1.y + x1.z * x1.z + x1.w * x1.w;
    float d2  = x2.x * x2.x + x2.y * x2.y + x2.z * x2.z + x2.w * x2.w;
    float d3  = x3.x * x3.x + x3.y * x3.y + x3.z * x3.z + x3.w * x3.w;

    float ss2 = d1 + (k2_is2 ? d2 : 0.0f);
    float ss3 = d3 + (k2_is2 ? 0.0f : d2);

    // warp butterfly reduction: 4 independent chains, SHFLs back-to-back
    // per stage so their latency overlaps.
#pragma unroll
    for (int o = 16; o > 0; o >>= 1) {
        const float t1 = __shfl_xor_sync(0xFFFFFFFFu, s1,  o);
        const float t2 = __shfl_xor_sync(0xFFFFFFFFu, ss1, o);
        const float t3 = __shfl_xor_sync(0xFFFFFFFFu, ss2, o);
        const float t4 = __shfl_xor_sync(0xFFFFFFFFu, ss3, o);
        s1 += t1; ss1 += t2; ss2 += t3; ss3 += t4;
    }

    const float mean = s1 * (1.0f / 128.0f);
    const float var  = ss1 * (1.0f / 128.0f) - mean * mean;
    const float inv1 = rsqrtf(var + EPS);
    const float inv2 = rsqrtf(ss2 * (1.0f / 192.0f) + EPS);
    const float inv3 = rsqrtf(ss3 * (1.0f / 160.0f) + EPS);

    float4* rout = (float4*)(out + (size_t)row * FEAT);

    float4 y0;
    y0.x = (x0.x - mean) * (inv1 * wr[0]) + br[0];
    y0.y = (x0.y - mean) * (inv1 * wr[1]) + br[1];
    y0.z = (x0.z - mean) * (inv1 * wr[2]) + br[2];
    y0.w = (x0.w - mean) * (inv1 * wr[3]) + br[3];
    __stcs(&rout[lane], y0);

    float4 y1;
    y1.x = x1.x * (inv2 * wr[4]);
    y1.y = x1.y * (inv2 * wr[5]);
    y1.z = x1.z * (inv2 * wr[6]);
    y1.w = x1.w * (inv2 * wr[7]);
    __stcs(&rout[lane + 32], y1);

    const float invk2 = k2_is2 ? inv2 : inv3;
    float4 y2;
    y2.x = x2.x * (invk2 * wr[8]);
    y2.y = x2.y * (invk2 * wr[9]);
    y2.z = x2.z * (invk2 * wr[10]);
    y2.w = x2.w * (invk2 * wr[11]);
    __stcs(&rout[lane + 64], y2);

    if (tail) {
        float4 y3;
        y3.x = x3.x * (inv3 * wr[12]);
        y3.y = x3.y * (inv3 * wr[13]);
        y3.z = x3.z * (inv3 * wr[14]);
        y3.w = x3.w * (inv3 * wr[15]);
        __stcs(&rout[lane + 96], y3);
    }
}

__global__ __launch_bounds__(256, 4)
void eqln_kernel(const float* __restrict__ in,
                 const float* __restrict__ w,
                 const float* __restrict__ b,
                 float* __restrict__ out)
{
    const int lane   = threadIdx.x & 31;
    const int warp   = (int)((blockIdx.x * blockDim.x + threadIdx.x) >> 5);
    const int nwarps = (int)((gridDim.x * blockDim.x) >> 5);

    // per-thread weights/biases in registers, amortized across ~42 rows
    float wr[16];
    float br[4];
#pragma unroll
    for (int k = 0; k < 4; k++) {
#pragma unroll
        for (int c = 0; c < 4; c++) {
            int e = 4 * (lane + 32 * k) + c;
            float wv = 0.0f;
            if (e < 128)       wv = __ldg(&w[e]);
            else if (e < 320)  wv = __ldg(&w[128 + (e - 128) / 3]);
            else if (e < 480)  wv = __ldg(&w[192 + (e - 320) / 5]);
            wr[4 * k + c] = wv;
        }
    }
#pragma unroll
    for (int c = 0; c < 4; c++) br[c] = __ldg(&b[4 * lane + c]);

    const bool tail   = (lane < 24);
    const bool k2_is2 = (lane < 16);

    // Paired grid-stride: warp w owns rows {2w, 2w+1}, striding by 2*nwarps.
    // Chip-wide wave still sweeps a contiguous window (good bank behavior),
    // but now each warp's two outstanding load batches are ADJACENT in DRAM
    // (3840B contiguous) instead of 9.1MB apart.
    const int stride = 2 * nwarps;
    int r = 2 * warp;                       // N_NODES is even -> r+1 valid whenever r is
    if (r >= N_NODES) return;

    RowBuf A, B;
    load_row(in, r,     lane, tail, A);
    load_row(in, r + 1, lane, tail, B);

    while (true) {
        const int rn = r + stride;
        const bool more = (rn < N_NODES);

        // Process A(r); B(r+1) already in flight/ready.
        process_row(out, r, lane, tail, k2_is2, wr, br, A);
        if (more) load_row(in, rn, lane, tail, A);        // prefetch next pair row 0

        process_row(out, r + 1, lane, tail, k2_is2, wr, br, B);
        if (!more) break;
        load_row(in, rn + 1, lane, tail, B);              // prefetch next pair row 1

        r = rn;
    }
}

extern "C" void kernel_launch(void* const* d_in, const int* in_sizes, int n_in,
                              void* d_out, int out_size)
{
    const float* node_input    = (const float*)d_in[0];   // (200000, 480) f32
    const float* affine_weight = (const float*)d_in[1];   // (224,) f32
    const float* affine_bias   = (const float*)d_in[2];   // (128,) f32
    float* out = (float*)d_out;

    const int threads = 256;
    const int blocks  = 148 * 4;   // 592 blocks -> 4736 warps, 4 CTAs/SM
    eqln_kernel<<<blocks, threads>>>(node_input, affine_weight, affine_bias, out);
}